// round 4
// baseline (speedup 1.0000x reference)
#include <cuda_runtime.h>
#include <cstdint>

// ---------------------------------------------------------------------------
// Problem constants (shapes fixed by the reference)
// ---------------------------------------------------------------------------
#define NMAX   100000
#define DIN    128
#define DHID   128
#define DDEC   512

// ---------------------------------------------------------------------------
// Device scratch (static globals: allocation-free per harness rules)
// ---------------------------------------------------------------------------
__device__ float4 g_msg[NMAX * 32];      // [N,128] neighbor sums  (51.2 MB)
__device__ float  g_cnt[NMAX];           // in-degree counts
__device__ float4 g_d[NMAX * 128];       // [N,512] decoder hidden (204.8 MB)
__device__ float  g_sum[DDEC];
__device__ float  g_sumsq[DDEC];
__device__ float4 g_scale4[DDEC / 4];    // gamma * rsqrt(var+eps)
__device__ float4 g_shift4[DDEC / 4];    // beta - mu*scale

// ---------------------------------------------------------------------------
// init: zero scratch + copy target = x into output section 3
// ---------------------------------------------------------------------------
__global__ void init_kernel(const float4* __restrict__ x,
                            float4* __restrict__ tgt, int M) {
    int stride = gridDim.x * blockDim.x;
    int tid = blockIdx.x * blockDim.x + threadIdx.x;
    int n4 = M * 32;
    for (int i = tid; i < n4; i += stride) {
        g_msg[i] = make_float4(0.f, 0.f, 0.f, 0.f);
        tgt[i] = x[i];
    }
    for (int i = tid; i < M; i += stride) g_cnt[i] = 0.f;
    if (tid < DDEC) { g_sum[tid] = 0.f; g_sumsq[tid] = 0.f; }
}

// ---------------------------------------------------------------------------
// scatter: warp handles 32 edges; lane l covers float4-column l of the row.
// edge_index is INT32 (JAX x64 disabled: jnp.int64 -> int32 in practice).
// vectorized global reduction (red.global.add.v4.f32, sm_90+)
// ---------------------------------------------------------------------------
__global__ void scatter_kernel(const int* __restrict__ ei,
                               const float4* __restrict__ x4, int E) {
    int lane = threadIdx.x & 31;
    int warp = (blockIdx.x * blockDim.x + threadIdx.x) >> 5;
    int nwarps = (gridDim.x * blockDim.x) >> 5;

    for (int e0 = warp * 32; e0 < E; e0 += nwarps * 32) {
        int s = 0, d = 0;
        int e = e0 + lane;
        if (e < E) {
            s = ei[e];
            d = ei[E + e];
            atomicAdd(&g_cnt[d], 1.0f);
        }
        int cnt = min(32, E - e0);
        for (int j = 0; j < cnt; j++) {
            int sj = __shfl_sync(0xffffffffu, s, j);
            int dj = __shfl_sync(0xffffffffu, d, j);
            float4 v = __ldg(&x4[(size_t)sj * 32 + lane]);
            float* p = (float*)&g_msg[(size_t)dj * 32 + lane];
            asm volatile("red.global.add.v4.f32 [%0], {%1,%2,%3,%4};"
                         :: "l"(p), "f"(v.x), "f"(v.y), "f"(v.z), "f"(v.w)
                         : "memory");
        }
    }
}

// ---------------------------------------------------------------------------
// finalize: msg /= max(cnt,1)  (in place)
// ---------------------------------------------------------------------------
__global__ void finalize_kernel(int M) {
    int i = blockIdx.x * blockDim.x + threadIdx.x;
    if (i >= M * 32) return;
    int m = i >> 5;
    float rc = 1.0f / fmaxf(g_cnt[m], 1.0f);
    float4 v = g_msg[i];
    v.x *= rc; v.y *= rc; v.z *= rc; v.w *= rc;
    g_msg[i] = v;
}

// ---------------------------------------------------------------------------
// Tiled SGEMM: C[M,NTOT] = A[M,KTOT] @ W[NTOT,KTOT]^T  (+ mode-specific fusion)
//   MODE 0 (ENC):  A = [aggr | x] (K=256), W = [Wl | Wr], epi: +bl, leaky(0.5)
//   MODE 1 (PROJ): A = h, epi: +bp, PReLU(a)
//   MODE 2 (DEC1): A = h, epi: +bd1, C -> g_d
//   MODE 3 (DEC2): A-load: leaky(bn(g_d), 0.01), epi: +bd2
// 128x128 block tile, BK=16, 256 threads, 8x8 per thread, double-buffered.
// ---------------------------------------------------------------------------
#define BM 128
#define BN 128
#define BK 16

template <int MODE, int KTOT, int NTOT>
__global__ __launch_bounds__(256, 2)
void gemm_kernel(const float* __restrict__ A, const float* __restrict__ A2,
                 const float* __restrict__ W, const float* __restrict__ W2,
                 const float* __restrict__ bias, const float* __restrict__ aprelu,
                 float* __restrict__ C, int M) {
    __shared__ __align__(16) float As[2][BK][BM];
    __shared__ __align__(16) float Bs[2][BK][BN];

    const float* Ap = (MODE == 0) ? (const float*)g_msg
                    : (MODE == 3) ? (const float*)g_d : A;
    float* Cp = (MODE == 2) ? (float*)g_d : C;

    const int tid = threadIdx.x;
    const int m0 = blockIdx.x * BM;
    const int n0 = blockIdx.y * BN;
    const int lr = tid >> 2;          // 0..63 (row in tile; also row+64)
    const int lc = (tid & 3) * 4;     // float4 col offset in k-tile
    const int ty8 = (tid >> 4) * 8;
    const int tx8 = (tid & 15) * 8;

    float4 pa[2], pb[2];

    auto loadA = [&](int k0) {
#pragma unroll
        for (int h = 0; h < 2; h++) {
            int m = m0 + lr + h * 64;
            int k = k0 + lc;
            float4 v = make_float4(0.f, 0.f, 0.f, 0.f);
            if (m < M) {
                if (MODE == 0) {
                    if (k < 128) v = __ldg((const float4*)(Ap + (size_t)m * 128 + k));
                    else         v = __ldg((const float4*)(A2 + (size_t)m * 128 + (k - 128)));
                } else if (MODE == 3) {
                    v = __ldg((const float4*)(Ap + (size_t)m * DDEC + k));
                    float4 sc = g_scale4[k >> 2];
                    float4 sh = g_shift4[k >> 2];
                    v.x = fmaf(v.x, sc.x, sh.x); v.x = v.x >= 0.f ? v.x : 0.01f * v.x;
                    v.y = fmaf(v.y, sc.y, sh.y); v.y = v.y >= 0.f ? v.y : 0.01f * v.y;
                    v.z = fmaf(v.z, sc.z, sh.z); v.z = v.z >= 0.f ? v.z : 0.01f * v.z;
                    v.w = fmaf(v.w, sc.w, sh.w); v.w = v.w >= 0.f ? v.w : 0.01f * v.w;
                } else {
                    v = __ldg((const float4*)(Ap + (size_t)m * KTOT + k));
                }
            }
            pa[h] = v;
        }
    };
    auto loadW = [&](int k0) {
#pragma unroll
        for (int h = 0; h < 2; h++) {
            int n = n0 + lr + h * 64;
            int k = k0 + lc;
            float4 v;
            if (MODE == 0) {
                if (k < 128) v = __ldg((const float4*)(W  + (size_t)n * 128 + k));
                else         v = __ldg((const float4*)(W2 + (size_t)n * 128 + (k - 128)));
            } else {
                v = __ldg((const float4*)(W + (size_t)n * KTOT + k));
            }
            pb[h] = v;
        }
    };
    auto stage = [&](int buf) {
#pragma unroll
        for (int h = 0; h < 2; h++) {
            int r = lr + h * 64;
            As[buf][lc + 0][r] = pa[h].x;
            As[buf][lc + 1][r] = pa[h].y;
            As[buf][lc + 2][r] = pa[h].z;
            As[buf][lc + 3][r] = pa[h].w;
            Bs[buf][lc + 0][r] = pb[h].x;
            Bs[buf][lc + 1][r] = pb[h].y;
            Bs[buf][lc + 2][r] = pb[h].z;
            Bs[buf][lc + 3][r] = pb[h].w;
        }
    };

    float acc[8][8];
#pragma unroll
    for (int i = 0; i < 8; i++)
#pragma unroll
        for (int j = 0; j < 8; j++) acc[i][j] = 0.f;

    loadA(0); loadW(0); stage(0);
    __syncthreads();

    constexpr int NKT = KTOT / BK;
    for (int t = 0; t < NKT; t++) {
        if (t + 1 < NKT) { loadA((t + 1) * BK); loadW((t + 1) * BK); }
        int buf = t & 1;
#pragma unroll
        for (int k = 0; k < BK; k++) {
            float a[8], b[8];
            float4 t0 = *(const float4*)&As[buf][k][ty8];
            float4 t1 = *(const float4*)&As[buf][k][ty8 + 4];
            float4 u0 = *(const float4*)&Bs[buf][k][tx8];
            float4 u1 = *(const float4*)&Bs[buf][k][tx8 + 4];
            a[0]=t0.x; a[1]=t0.y; a[2]=t0.z; a[3]=t0.w;
            a[4]=t1.x; a[5]=t1.y; a[6]=t1.z; a[7]=t1.w;
            b[0]=u0.x; b[1]=u0.y; b[2]=u0.z; b[3]=u0.w;
            b[4]=u1.x; b[5]=u1.y; b[6]=u1.z; b[7]=u1.w;
#pragma unroll
            for (int i = 0; i < 8; i++)
#pragma unroll
                for (int j = 0; j < 8; j++)
                    acc[i][j] = fmaf(a[i], b[j], acc[i][j]);
        }
        if (t + 1 < NKT) {
            stage((t + 1) & 1);
            __syncthreads();
        }
    }

    // epilogue
    float ap = (MODE == 1) ? __ldg(aprelu) : 0.f;
    float bb[8];
#pragma unroll
    for (int j = 0; j < 8; j++) bb[j] = __ldg(&bias[n0 + tx8 + j]);

#pragma unroll
    for (int i = 0; i < 8; i++) {
        int m = m0 + ty8 + i;
        if (m >= M) continue;
#pragma unroll
        for (int jj = 0; jj < 2; jj++) {
            float v[4];
#pragma unroll
            for (int c = 0; c < 4; c++) {
                float t = acc[i][jj * 4 + c] + bb[jj * 4 + c];
                if (MODE == 0) t = t >= 0.f ? t : 0.5f * t;   // encoder leaky
                if (MODE == 1) t = t >= 0.f ? t : ap * t;     // PReLU
                v[c] = t;
            }
            float4 o = make_float4(v[0], v[1], v[2], v[3]);
            *(float4*)&Cp[(size_t)m * NTOT + n0 + tx8 + jj * 4] = o;
        }
    }
}

// ---------------------------------------------------------------------------
// BN batch statistics over g_d: per-column sum / sumsq
// ---------------------------------------------------------------------------
__global__ void bn_stats_kernel(int M) {
    int col4 = threadIdx.x & 127;   // float4 column 0..127  (512 cols)
    int ro = threadIdx.x >> 7;      // 0/1
    float4 s = make_float4(0.f, 0.f, 0.f, 0.f);
    float4 q = make_float4(0.f, 0.f, 0.f, 0.f);
    for (int m = blockIdx.x * 2 + ro; m < M; m += gridDim.x * 2) {
        float4 v = g_d[(size_t)m * 128 + col4];
        s.x += v.x; s.y += v.y; s.z += v.z; s.w += v.w;
        q.x = fmaf(v.x, v.x, q.x); q.y = fmaf(v.y, v.y, q.y);
        q.z = fmaf(v.z, v.z, q.z); q.w = fmaf(v.w, v.w, q.w);
    }
    int c = col4 * 4;
    atomicAdd(&g_sum[c + 0], s.x); atomicAdd(&g_sum[c + 1], s.y);
    atomicAdd(&g_sum[c + 2], s.z); atomicAdd(&g_sum[c + 3], s.w);
    atomicAdd(&g_sumsq[c + 0], q.x); atomicAdd(&g_sumsq[c + 1], q.y);
    atomicAdd(&g_sumsq[c + 2], q.z); atomicAdd(&g_sumsq[c + 3], q.w);
}

__global__ void bn_finalize_kernel(int M, const float* __restrict__ gamma,
                                   const float* __restrict__ beta) {
    int c = threadIdx.x;
    if (c >= DDEC) return;
    float invM = 1.0f / (float)M;
    float mu = g_sum[c] * invM;
    float var = g_sumsq[c] * invM - mu * mu;
    float rs = rsqrtf(var + 1e-5f);
    float sc = gamma[c] * rs;
    ((float*)g_scale4)[c] = sc;
    ((float*)g_shift4)[c] = beta[c] - mu * sc;
}

// ---------------------------------------------------------------------------
// host launcher
// ---------------------------------------------------------------------------
extern "C" void kernel_launch(void* const* d_in, const int* in_sizes, int n_in,
                              void* d_out, int out_size) {
    const float* x     = (const float*)d_in[0];
    const int*   ei    = (const int*)d_in[1];      // int32 (JAX x64 disabled)
    const float* Wl    = (const float*)d_in[2];
    const float* bl    = (const float*)d_in[3];
    const float* Wr    = (const float*)d_in[4];
    const float* Wp    = (const float*)d_in[5];
    const float* bp    = (const float*)d_in[6];
    const float* ap    = (const float*)d_in[7];
    const float* Wd1   = (const float*)d_in[8];
    const float* bd1   = (const float*)d_in[9];
    const float* gamma = (const float*)d_in[10];
    const float* beta  = (const float*)d_in[11];
    const float* Wd2   = (const float*)d_in[12];
    const float* bd2   = (const float*)d_in[13];

    const int M = in_sizes[0] / DIN;
    const int E = in_sizes[1] / 2;

    float* out = (float*)d_out;
    float* h_out   = out;
    float* z_out   = out + (size_t)M * DHID;
    float* rec_out = out + (size_t)2 * M * DHID;
    float* tgt_out = out + (size_t)3 * M * DHID;

    // 1. zero scratch + copy target
    init_kernel<<<2048, 256>>>((const float4*)x, (float4*)tgt_out, M);

    // 2. edge scatter (mean numerator + counts)
    scatter_kernel<<<(E + 255) / 256, 256>>>(ei, (const float4*)x, E);

    // 3. divide by degree
    finalize_kernel<<<(M * 32 + 255) / 256, 256>>>(M);

    const int gm = (M + BM - 1) / BM;

    // 4. encoder: h = leaky([aggr|x] @ [Wl|Wr]^T + bl, 0.5)
    gemm_kernel<0, 256, 128><<<dim3(gm, 1), 256>>>(nullptr, x, Wl, Wr, bl, ap, h_out, M);

    // 5. projection: z = PReLU(h @ Wp^T + bp)
    gemm_kernel<1, 128, 128><<<dim3(gm, 1), 256>>>(h_out, nullptr, Wp, nullptr, bp, ap, z_out, M);

    // 6. decoder layer 1: g_d = h @ Wd1^T + bd1
    gemm_kernel<2, 128, 512><<<dim3(gm, 4), 256>>>(h_out, nullptr, Wd1, nullptr, bd1, ap, nullptr, M);

    // 7. BN statistics + finalize
    bn_stats_kernel<<<512, 256>>>(M);
    bn_finalize_kernel<<<1, 512>>>(M, gamma, beta);

    // 8. decoder layer 2: rec = leaky(bn(g_d),0.01) @ Wd2^T + bd2
    gemm_kernel<3, 512, 128><<<dim3(gm, 1), 256>>>(nullptr, nullptr, Wd2, nullptr, bd2, ap, rec_out, M);
}

// round 6
// speedup vs baseline: 1.8303x; 1.8303x over previous
#include <cuda_runtime.h>
#include <cstdint>

// ---------------------------------------------------------------------------
// Problem constants (shapes fixed by the reference)
// ---------------------------------------------------------------------------
#define NMAX   100000
#define DIN    128
#define DHID   128
#define DDEC   512

// ---------------------------------------------------------------------------
// Device scratch (static globals: allocation-free per harness rules)
// ---------------------------------------------------------------------------
__device__ float4 g_msg[NMAX * 32];      // [N,128] neighbor sums  (51.2 MB)
__device__ float  g_cnt[NMAX];           // in-degree counts
__device__ float4 g_d[NMAX * 128];       // [N,512] decoder hidden (204.8 MB)
__device__ float  g_sum[DDEC];
__device__ float  g_sumsq[DDEC];
__device__ float4 g_scale4[DDEC / 4];    // gamma * rsqrt(var+eps)
__device__ float4 g_shift4[DDEC / 4];    // beta - mu*scale

// ---------------------------------------------------------------------------
// init: zero scratch + copy target = x into output section 3
// ---------------------------------------------------------------------------
__global__ void init_kernel(const float4* __restrict__ x,
                            float4* __restrict__ tgt, int M) {
    int stride = gridDim.x * blockDim.x;
    int tid = blockIdx.x * blockDim.x + threadIdx.x;
    int n4 = M * 32;
    for (int i = tid; i < n4; i += stride) {
        g_msg[i] = make_float4(0.f, 0.f, 0.f, 0.f);
        tgt[i] = x[i];
    }
    for (int i = tid; i < M; i += stride) g_cnt[i] = 0.f;
    if (tid < DDEC) { g_sum[tid] = 0.f; g_sumsq[tid] = 0.f; }
}

// ---------------------------------------------------------------------------
// scatter: warp handles 32 edges; lane l covers float4-column l of the row.
// ---------------------------------------------------------------------------
__global__ void scatter_kernel(const int* __restrict__ ei,
                               const float4* __restrict__ x4, int E) {
    int lane = threadIdx.x & 31;
    int warp = (blockIdx.x * blockDim.x + threadIdx.x) >> 5;
    int nwarps = (gridDim.x * blockDim.x) >> 5;

    for (int e0 = warp * 32; e0 < E; e0 += nwarps * 32) {
        int s = 0, d = 0;
        int e = e0 + lane;
        if (e < E) {
            s = ei[e];
            d = ei[E + e];
            atomicAdd(&g_cnt[d], 1.0f);
        }
        int cnt = min(32, E - e0);
        for (int j = 0; j < cnt; j++) {
            int sj = __shfl_sync(0xffffffffu, s, j);
            int dj = __shfl_sync(0xffffffffu, d, j);
            float4 v = __ldg(&x4[(size_t)sj * 32 + lane]);
            float* p = (float*)&g_msg[(size_t)dj * 32 + lane];
            asm volatile("red.global.add.v4.f32 [%0], {%1,%2,%3,%4};"
                         :: "l"(p), "f"(v.x), "f"(v.y), "f"(v.z), "f"(v.w)
                         : "memory");
        }
    }
}

// ---------------------------------------------------------------------------
// finalize: msg /= max(cnt,1)  (in place)
// ---------------------------------------------------------------------------
__global__ void finalize_kernel(int M) {
    int i = blockIdx.x * blockDim.x + threadIdx.x;
    if (i >= M * 32) return;
    int m = i >> 5;
    float rc = 1.0f / fmaxf(g_cnt[m], 1.0f);
    float4 v = g_msg[i];
    v.x *= rc; v.y *= rc; v.z *= rc; v.w *= rc;
    g_msg[i] = v;
}

// ---------------------------------------------------------------------------
// TF32 tensor-core GEMM: C[M,NTOT] = A[M,KTOT] @ W[NTOT,KTOT]^T (+ fusion)
//   MODE 0 (ENC):  A = [aggr | x] (K=256), W = [Wl | Wr], epi: +bl, leaky(0.5)
//   MODE 1 (PROJ): A = h, epi: +bp, PReLU(a)
//   MODE 2 (DEC1): A = h, epi: +bd1, C -> g_d
//   MODE 3 (DEC2): A-load: leaky(bn(g_d), 0.01), epi: +bd2
//
// 128x128 block tile, BK=16, 256 threads (8 warps, 2x4), warp tile 64x32,
// mma.sync.m16n8k8 tf32, double-buffered smem.
// smem layout: [row][20] floats (stride 20 -> conflict-free fragment LDS:
//   banks per 8 rows = {0,20,8,28,16,4,24,12}+col, all 32 distinct).
// ---------------------------------------------------------------------------
#define BM 128
#define BN 128
#define BK 16
#define LSTR 20

// f32 -> tf32 bits (destination must be .b32 register per PTX ISA)
__device__ __forceinline__ uint32_t f2tf32(float f) {
    uint32_t u;
    asm("cvt.rna.tf32.f32 %0, %1;" : "=r"(u) : "f"(f));
    return u;
}
__device__ __forceinline__ float4 cvt_tf32x4(float4 v) {
    v.x = __uint_as_float(f2tf32(v.x));
    v.y = __uint_as_float(f2tf32(v.y));
    v.z = __uint_as_float(f2tf32(v.z));
    v.w = __uint_as_float(f2tf32(v.w));
    return v;
}

__device__ __forceinline__ void mma_tf32(float* c, const uint32_t* a, const uint32_t* b) {
    asm volatile(
        "mma.sync.aligned.m16n8k8.row.col.f32.tf32.tf32.f32 "
        "{%0,%1,%2,%3}, {%4,%5,%6,%7}, {%8,%9}, {%0,%1,%2,%3};"
        : "+f"(c[0]), "+f"(c[1]), "+f"(c[2]), "+f"(c[3])
        : "r"(a[0]), "r"(a[1]), "r"(a[2]), "r"(a[3]), "r"(b[0]), "r"(b[1]));
}

template <int MODE, int KTOT, int NTOT>
__global__ __launch_bounds__(256, 2)
void gemm_tc(const float* __restrict__ A, const float* __restrict__ A2,
             const float* __restrict__ W, const float* __restrict__ W2,
             const float* __restrict__ bias, const float* __restrict__ aprelu,
             float* __restrict__ C, int M) {
    __shared__ __align__(16) float As[2][BM][LSTR];
    __shared__ __align__(16) float Bs[2][BN][LSTR];

    const float* Ap = (MODE == 0) ? (const float*)g_msg
                    : (MODE == 3) ? (const float*)g_d : A;
    float* Cp = (MODE == 2) ? (float*)g_d : C;

    const int tid  = threadIdx.x;
    const int lane = tid & 31;
    const int wid  = tid >> 5;
    const int wm   = (wid & 1) * 64;   // warp m offset within tile
    const int wn   = (wid >> 1) * 32;  // warp n offset within tile
    const int m0   = blockIdx.x * BM;
    const int n0   = blockIdx.y * BN;

    const int lr  = tid >> 2;          // 0..63
    const int lc4 = (tid & 3) * 4;     // 0,4,8,12 (k offset of float4)

    float4 pa[2], pb[2];

    auto loadA = [&](int k0) {
#pragma unroll
        for (int h = 0; h < 2; h++) {
            int m = m0 + lr + h * 64;
            int k = k0 + lc4;
            float4 v = make_float4(0.f, 0.f, 0.f, 0.f);
            if (m < M) {
                if (MODE == 0) {
                    if (k < 128) v = __ldg((const float4*)(Ap + (size_t)m * 128 + k));
                    else         v = __ldg((const float4*)(A2 + (size_t)m * 128 + (k - 128)));
                } else if (MODE == 3) {
                    v = __ldg((const float4*)(Ap + (size_t)m * DDEC + k));
                    float4 sc = g_scale4[k >> 2];
                    float4 sh = g_shift4[k >> 2];
                    v.x = fmaf(v.x, sc.x, sh.x); v.x = v.x >= 0.f ? v.x : 0.01f * v.x;
                    v.y = fmaf(v.y, sc.y, sh.y); v.y = v.y >= 0.f ? v.y : 0.01f * v.y;
                    v.z = fmaf(v.z, sc.z, sh.z); v.z = v.z >= 0.f ? v.z : 0.01f * v.z;
                    v.w = fmaf(v.w, sc.w, sh.w); v.w = v.w >= 0.f ? v.w : 0.01f * v.w;
                } else {
                    v = __ldg((const float4*)(Ap + (size_t)m * KTOT + k));
                }
            }
            pa[h] = cvt_tf32x4(v);
        }
    };
    auto loadW = [&](int k0) {
#pragma unroll
        for (int h = 0; h < 2; h++) {
            int n = n0 + lr + h * 64;
            int k = k0 + lc4;
            float4 v;
            if (MODE == 0) {
                if (k < 128) v = __ldg((const float4*)(W  + (size_t)n * 128 + k));
                else         v = __ldg((const float4*)(W2 + (size_t)n * 128 + (k - 128)));
            } else {
                v = __ldg((const float4*)(W + (size_t)n * KTOT + k));
            }
            pb[h] = cvt_tf32x4(v);
        }
    };
    auto stage = [&](int buf) {
#pragma unroll
        for (int h = 0; h < 2; h++) {
            *(float4*)&As[buf][lr + h * 64][lc4] = pa[h];
            *(float4*)&Bs[buf][lr + h * 64][lc4] = pb[h];
        }
    };

    float acc[4][4][4];   // [mt][nt][c0..c3]
#pragma unroll
    for (int i = 0; i < 4; i++)
#pragma unroll
        for (int j = 0; j < 4; j++)
#pragma unroll
            for (int c = 0; c < 4; c++) acc[i][j][c] = 0.f;

    loadA(0); loadW(0); stage(0);
    __syncthreads();

    constexpr int NKT = KTOT / BK;
    const int arow = wm + (lane >> 2);
    const int brow = wn + (lane >> 2);
    const int kl   = lane & 3;

    for (int t = 0; t < NKT; t++) {
        if (t + 1 < NKT) { loadA((t + 1) * BK); loadW((t + 1) * BK); }
        int buf = t & 1;
#pragma unroll
        for (int ks = 0; ks < 2; ks++) {
            const int kb = ks * 8 + kl;
            uint32_t af[4][4];
            uint32_t bf[4][2];
#pragma unroll
            for (int mt = 0; mt < 4; mt++) {
                af[mt][0] = __float_as_uint(As[buf][arow + mt * 16][kb]);
                af[mt][1] = __float_as_uint(As[buf][arow + mt * 16 + 8][kb]);
                af[mt][2] = __float_as_uint(As[buf][arow + mt * 16][kb + 4]);
                af[mt][3] = __float_as_uint(As[buf][arow + mt * 16 + 8][kb + 4]);
            }
#pragma unroll
            for (int nt = 0; nt < 4; nt++) {
                bf[nt][0] = __float_as_uint(Bs[buf][brow + nt * 8][kb]);
                bf[nt][1] = __float_as_uint(Bs[buf][brow + nt * 8][kb + 4]);
            }
#pragma unroll
            for (int mt = 0; mt < 4; mt++)
#pragma unroll
                for (int nt = 0; nt < 4; nt++)
                    mma_tf32(acc[mt][nt], af[mt], bf[nt]);
        }
        if (t + 1 < NKT) {
            stage((t + 1) & 1);
            __syncthreads();
        }
    }

    // epilogue
    const float ap = (MODE == 1) ? __ldg(aprelu) : 0.f;
#pragma unroll
    for (int nt = 0; nt < 4; nt++) {
        const int col = n0 + wn + nt * 8 + (lane & 3) * 2;
        const float b0 = __ldg(&bias[col]);
        const float b1 = __ldg(&bias[col + 1]);
#pragma unroll
        for (int mt = 0; mt < 4; mt++) {
            const int row = m0 + wm + mt * 16 + (lane >> 2);
#pragma unroll
            for (int h = 0; h < 2; h++) {
                int r = row + 8 * h;
                if (r >= M) continue;
                float v0 = acc[mt][nt][2 * h + 0] + b0;
                float v1 = acc[mt][nt][2 * h + 1] + b1;
                if (MODE == 0) { v0 = v0 >= 0.f ? v0 : 0.5f * v0; v1 = v1 >= 0.f ? v1 : 0.5f * v1; }
                if (MODE == 1) { v0 = v0 >= 0.f ? v0 : ap * v0;  v1 = v1 >= 0.f ? v1 : ap * v1; }
                *(float2*)&Cp[(size_t)r * NTOT + col] = make_float2(v0, v1);
            }
        }
    }
}

// ---------------------------------------------------------------------------
// BN batch statistics over g_d: per-column sum / sumsq
// ---------------------------------------------------------------------------
__global__ void bn_stats_kernel(int M) {
    int col4 = threadIdx.x & 127;
    int ro = threadIdx.x >> 7;
    float4 s = make_float4(0.f, 0.f, 0.f, 0.f);
    float4 q = make_float4(0.f, 0.f, 0.f, 0.f);
    for (int m = blockIdx.x * 2 + ro; m < M; m += gridDim.x * 2) {
        float4 v = g_d[(size_t)m * 128 + col4];
        s.x += v.x; s.y += v.y; s.z += v.z; s.w += v.w;
        q.x = fmaf(v.x, v.x, q.x); q.y = fmaf(v.y, v.y, q.y);
        q.z = fmaf(v.z, v.z, q.z); q.w = fmaf(v.w, v.w, q.w);
    }
    int c = col4 * 4;
    atomicAdd(&g_sum[c + 0], s.x); atomicAdd(&g_sum[c + 1], s.y);
    atomicAdd(&g_sum[c + 2], s.z); atomicAdd(&g_sum[c + 3], s.w);
    atomicAdd(&g_sumsq[c + 0], q.x); atomicAdd(&g_sumsq[c + 1], q.y);
    atomicAdd(&g_sumsq[c + 2], q.z); atomicAdd(&g_sumsq[c + 3], q.w);
}

__global__ void bn_finalize_kernel(int M, const float* __restrict__ gamma,
                                   const float* __restrict__ beta) {
    int c = threadIdx.x;
    if (c >= DDEC) return;
    float invM = 1.0f / (float)M;
    float mu = g_sum[c] * invM;
    float var = g_sumsq[c] * invM - mu * mu;
    float rs = rsqrtf(var + 1e-5f);
    float sc = gamma[c] * rs;
    ((float*)g_scale4)[c] = sc;
    ((float*)g_shift4)[c] = beta[c] - mu * sc;
}

// ---------------------------------------------------------------------------
// host launcher
// ---------------------------------------------------------------------------
extern "C" void kernel_launch(void* const* d_in, const int* in_sizes, int n_in,
                              void* d_out, int out_size) {
    const float* x     = (const float*)d_in[0];
    const int*   ei    = (const int*)d_in[1];      // int32 (JAX x64 disabled)
    const float* Wl    = (const float*)d_in[2];
    const float* bl    = (const float*)d_in[3];
    const float* Wr    = (const float*)d_in[4];
    const float* Wp    = (const float*)d_in[5];
    const float* bp    = (const float*)d_in[6];
    const float* ap    = (const float*)d_in[7];
    const float* Wd1   = (const float*)d_in[8];
    const float* bd1   = (const float*)d_in[9];
    const float* gamma = (const float*)d_in[10];
    const float* beta  = (const float*)d_in[11];
    const float* Wd2   = (const float*)d_in[12];
    const float* bd2   = (const float*)d_in[13];

    const int M = in_sizes[0] / DIN;
    const int E = in_sizes[1] / 2;

    float* out = (float*)d_out;
    float* h_out   = out;
    float* z_out   = out + (size_t)M * DHID;
    float* rec_out = out + (size_t)2 * M * DHID;
    float* tgt_out = out + (size_t)3 * M * DHID;

    // 1. zero scratch + copy target
    init_kernel<<<2048, 256>>>((const float4*)x, (float4*)tgt_out, M);

    // 2. edge scatter (mean numerator + counts)
    scatter_kernel<<<(E + 255) / 256, 256>>>(ei, (const float4*)x, E);

    // 3. divide by degree
    finalize_kernel<<<(M * 32 + 255) / 256, 256>>>(M);

    const int gm = (M + BM - 1) / BM;

    // 4. encoder: h = leaky([aggr|x] @ [Wl|Wr]^T + bl, 0.5)
    gemm_tc<0, 256, 128><<<dim3(gm, 1), 256>>>(nullptr, x, Wl, Wr, bl, ap, h_out, M);

    // 5. projection: z = PReLU(h @ Wp^T + bp)
    gemm_tc<1, 128, 128><<<dim3(gm, 1), 256>>>(h_out, nullptr, Wp, nullptr, bp, ap, z_out, M);

    // 6. decoder layer 1: g_d = h @ Wd1^T + bd1
    gemm_tc<2, 128, 512><<<dim3(gm, 4), 256>>>(h_out, nullptr, Wd1, nullptr, bd1, ap, nullptr, M);

    // 7. BN statistics + finalize
    bn_stats_kernel<<<512, 256>>>(M);
    bn_finalize_kernel<<<1, 512>>>(M, gamma, beta);

    // 8. decoder layer 2: rec = leaky(bn(g_d),0.01) @ Wd2^T + bd2
    gemm_tc<3, 512, 128><<<dim3(gm, 1), 256>>>(nullptr, nullptr, Wd2, nullptr, bd2, ap, rec_out, M);
}

// round 7
// speedup vs baseline: 1.9732x; 1.0781x over previous
#include <cuda_runtime.h>
#include <cstdint>

// ---------------------------------------------------------------------------
// Problem constants
// ---------------------------------------------------------------------------
#define NMAX   100000
#define DIN    128
#define DHID   128
#define DDEC   512

// ---------------------------------------------------------------------------
// Device scratch
// ---------------------------------------------------------------------------
__device__ float4 g_msg[NMAX * 32];      // [N,128] neighbor sums (51.2 MB)
__device__ float  g_cnt[NMAX];           // in-degree counts
__device__ float  g_H[DHID * DHID];      // centered second-moment  h_c^T h_c
__device__ float  g_hsum[DHID];          // column sums of h
__device__ float  g_scale[DDEC];         // gamma * rsqrt(var+eps)
__device__ float  g_shift[DDEC];         // beta - (w.mh)*scale   (bd1 cancels)

// ---------------------------------------------------------------------------
// tf32 helpers
// ---------------------------------------------------------------------------
__device__ __forceinline__ uint32_t f2tf32(float f) {
    uint32_t u;
    asm("cvt.rna.tf32.f32 %0, %1;" : "=r"(u) : "f"(f));
    return u;
}
__device__ __forceinline__ float4 cvt_tf32x4(float4 v) {
    v.x = __uint_as_float(f2tf32(v.x));
    v.y = __uint_as_float(f2tf32(v.y));
    v.z = __uint_as_float(f2tf32(v.z));
    v.w = __uint_as_float(f2tf32(v.w));
    return v;
}
__device__ __forceinline__ void mma_tf32(float* c, const uint32_t* a, const uint32_t* b) {
    asm volatile(
        "mma.sync.aligned.m16n8k8.row.col.f32.tf32.tf32.f32 "
        "{%0,%1,%2,%3}, {%4,%5,%6,%7}, {%8,%9}, {%0,%1,%2,%3};"
        : "+f"(c[0]), "+f"(c[1]), "+f"(c[2]), "+f"(c[3])
        : "r"(a[0]), "r"(a[1]), "r"(a[2]), "r"(a[3]), "r"(b[0]), "r"(b[1]));
}

// Shared 128x128x128 MMA block: A[m][k] and B[n][k] both in smem with
// stride 132 (132 mod 32 == 4 -> fragment bank pattern 4*q+kl covers all
// 32 banks exactly once: conflict-free). 8 warps 2x4, warp tile 64x32.
#define SSTR 132
__device__ __forceinline__ void mma_block_k128(
    const float (*A)[SSTR], const float (*B)[SSTR],
    float acc[4][4][4], int arow, int brow, int kl) {
#pragma unroll
    for (int t = 0; t < 8; t++) {
#pragma unroll
        for (int ks = 0; ks < 2; ks++) {
            const int kb = t * 16 + ks * 8 + kl;
            uint32_t af[4][4], bf[4][2];
#pragma unroll
            for (int mt = 0; mt < 4; mt++) {
                af[mt][0] = __float_as_uint(A[arow + mt * 16][kb]);
                af[mt][1] = __float_as_uint(A[arow + mt * 16 + 8][kb]);
                af[mt][2] = __float_as_uint(A[arow + mt * 16][kb + 4]);
                af[mt][3] = __float_as_uint(A[arow + mt * 16 + 8][kb + 4]);
            }
#pragma unroll
            for (int nt = 0; nt < 4; nt++) {
                bf[nt][0] = __float_as_uint(B[brow + nt * 8][kb]);
                bf[nt][1] = __float_as_uint(B[brow + nt * 8][kb + 4]);
            }
#pragma unroll
            for (int mt = 0; mt < 4; mt++)
#pragma unroll
                for (int nt = 0; nt < 4; nt++)
                    mma_tf32(acc[mt][nt], af[mt], bf[nt]);
        }
    }
}

// ---------------------------------------------------------------------------
// init: zero scratch + copy target
// ---------------------------------------------------------------------------
__global__ void init_kernel(const float4* __restrict__ x,
                            float4* __restrict__ tgt, int M) {
    int stride = gridDim.x * blockDim.x;
    int tid = blockIdx.x * blockDim.x + threadIdx.x;
    int n4 = M * 32;
    for (int i = tid; i < n4; i += stride) {
        g_msg[i] = make_float4(0.f, 0.f, 0.f, 0.f);
        tgt[i] = x[i];
    }
    for (int i = tid; i < M; i += stride) g_cnt[i] = 0.f;
    for (int i = tid; i < DHID * DHID; i += stride) g_H[i] = 0.f;
    if (tid < DHID) g_hsum[tid] = 0.f;
}

// ---------------------------------------------------------------------------
// scatter
// ---------------------------------------------------------------------------
__global__ void scatter_kernel(const int* __restrict__ ei,
                               const float4* __restrict__ x4, int E) {
    int lane = threadIdx.x & 31;
    int warp = (blockIdx.x * blockDim.x + threadIdx.x) >> 5;
    int nwarps = (gridDim.x * blockDim.x) >> 5;

    for (int e0 = warp * 32; e0 < E; e0 += nwarps * 32) {
        int s = 0, d = 0;
        int e = e0 + lane;
        if (e < E) {
            s = ei[e];
            d = ei[E + e];
            atomicAdd(&g_cnt[d], 1.0f);
        }
        int cnt = min(32, E - e0);
        for (int j = 0; j < cnt; j++) {
            int sj = __shfl_sync(0xffffffffu, s, j);
            int dj = __shfl_sync(0xffffffffu, d, j);
            float4 v = __ldg(&x4[(size_t)sj * 32 + lane]);
            float* p = (float*)&g_msg[(size_t)dj * 32 + lane];
            asm volatile("red.global.add.v4.f32 [%0], {%1,%2,%3,%4};"
                         :: "l"(p), "f"(v.x), "f"(v.y), "f"(v.z), "f"(v.w)
                         : "memory");
        }
    }
}

// ---------------------------------------------------------------------------
// TF32 GEMM for ENC / PROJ (unchanged structure; degree division fused in ENC)
//   MODE 0 (ENC):  A = [msg/deg | x] (K=256), W = [Wl | Wr], epi: +bl, leaky(0.5)
//   MODE 1 (PROJ): A = h, epi: +bp, PReLU(a)
// ---------------------------------------------------------------------------
#define BM 128
#define BN 128
#define BK 16
#define LSTR 20

template <int MODE, int KTOT, int NTOT>
__global__ __launch_bounds__(256, 2)
void gemm_tc(const float* __restrict__ A, const float* __restrict__ A2,
             const float* __restrict__ W, const float* __restrict__ W2,
             const float* __restrict__ bias, const float* __restrict__ aprelu,
             float* __restrict__ C, int M) {
    __shared__ __align__(16) float As[2][BM][LSTR];
    __shared__ __align__(16) float Bs[2][BN][LSTR];

    const float* Ap = (MODE == 0) ? (const float*)g_msg : A;

    const int tid  = threadIdx.x;
    const int lane = tid & 31;
    const int wid  = tid >> 5;
    const int wm   = (wid & 1) * 64;
    const int wn   = (wid >> 1) * 32;
    const int m0   = blockIdx.x * BM;
    const int n0   = blockIdx.y * BN;

    const int lr  = tid >> 2;
    const int lc4 = (tid & 3) * 4;

    float4 pa[2], pb[2];

    auto loadA = [&](int k0) {
#pragma unroll
        for (int h = 0; h < 2; h++) {
            int m = m0 + lr + h * 64;
            int k = k0 + lc4;
            float4 v = make_float4(0.f, 0.f, 0.f, 0.f);
            if (m < M) {
                if (MODE == 0) {
                    if (k < 128) {
                        v = __ldg((const float4*)(Ap + (size_t)m * 128 + k));
                        float rc = 1.0f / fmaxf(g_cnt[m], 1.0f);
                        v.x *= rc; v.y *= rc; v.z *= rc; v.w *= rc;
                    } else {
                        v = __ldg((const float4*)(A2 + (size_t)m * 128 + (k - 128)));
                    }
                } else {
                    v = __ldg((const float4*)(Ap + (size_t)m * KTOT + k));
                }
            }
            pa[h] = cvt_tf32x4(v);
        }
    };
    auto loadW = [&](int k0) {
#pragma unroll
        for (int h = 0; h < 2; h++) {
            int n = n0 + lr + h * 64;
            int k = k0 + lc4;
            float4 v;
            if (MODE == 0) {
                if (k < 128) v = __ldg((const float4*)(W  + (size_t)n * 128 + k));
                else         v = __ldg((const float4*)(W2 + (size_t)n * 128 + (k - 128)));
            } else {
                v = __ldg((const float4*)(W + (size_t)n * KTOT + k));
            }
            pb[h] = cvt_tf32x4(v);
        }
    };
    auto stage = [&](int buf) {
#pragma unroll
        for (int h = 0; h < 2; h++) {
            *(float4*)&As[buf][lr + h * 64][lc4] = pa[h];
            *(float4*)&Bs[buf][lr + h * 64][lc4] = pb[h];
        }
    };

    float acc[4][4][4];
#pragma unroll
    for (int i = 0; i < 4; i++)
#pragma unroll
        for (int j = 0; j < 4; j++)
#pragma unroll
            for (int c = 0; c < 4; c++) acc[i][j][c] = 0.f;

    loadA(0); loadW(0); stage(0);
    __syncthreads();

    constexpr int NKT = KTOT / BK;
    const int arow = wm + (lane >> 2);
    const int brow = wn + (lane >> 2);
    const int kl   = lane & 3;

    for (int t = 0; t < NKT; t++) {
        if (t + 1 < NKT) { loadA((t + 1) * BK); loadW((t + 1) * BK); }
        int buf = t & 1;
#pragma unroll
        for (int ks = 0; ks < 2; ks++) {
            const int kb = ks * 8 + kl;
            uint32_t af[4][4], bf[4][2];
#pragma unroll
            for (int mt = 0; mt < 4; mt++) {
                af[mt][0] = __float_as_uint(As[buf][arow + mt * 16][kb]);
                af[mt][1] = __float_as_uint(As[buf][arow + mt * 16 + 8][kb]);
                af[mt][2] = __float_as_uint(As[buf][arow + mt * 16][kb + 4]);
                af[mt][3] = __float_as_uint(As[buf][arow + mt * 16 + 8][kb + 4]);
            }
#pragma unroll
            for (int nt = 0; nt < 4; nt++) {
                bf[nt][0] = __float_as_uint(Bs[buf][brow + nt * 8][kb]);
                bf[nt][1] = __float_as_uint(Bs[buf][brow + nt * 8][kb + 4]);
            }
#pragma unroll
            for (int mt = 0; mt < 4; mt++)
#pragma unroll
                for (int nt = 0; nt < 4; nt++)
                    mma_tf32(acc[mt][nt], af[mt], bf[nt]);
        }
        if (t + 1 < NKT) {
            stage((t + 1) & 1);
            __syncthreads();
        }
    }

    const float ap = (MODE == 1) ? __ldg(aprelu) : 0.f;
#pragma unroll
    for (int nt = 0; nt < 4; nt++) {
        const int col = n0 + wn + nt * 8 + (lane & 3) * 2;
        const float b0 = __ldg(&bias[col]);
        const float b1 = __ldg(&bias[col + 1]);
#pragma unroll
        for (int mt = 0; mt < 4; mt++) {
            const int row = m0 + wm + mt * 16 + (lane >> 2);
#pragma unroll
            for (int h = 0; h < 2; h++) {
                int r = row + 8 * h;
                if (r >= M) continue;
                float v0 = acc[mt][nt][2 * h + 0] + b0;
                float v1 = acc[mt][nt][2 * h + 1] + b1;
                if (MODE == 0) { v0 = v0 >= 0.f ? v0 : 0.5f * v0; v1 = v1 >= 0.f ? v1 : 0.5f * v1; }
                if (MODE == 1) { v0 = v0 >= 0.f ? v0 : ap * v0;  v1 = v1 >= 0.f ? v1 : ap * v1; }
                *(float2*)&C[(size_t)r * NTOT + col] = make_float2(v0, v1);
            }
        }
    }
}

// ---------------------------------------------------------------------------
// colsum: g_hsum[c] = sum_m h[m][c]
// ---------------------------------------------------------------------------
__global__ void colsum_kernel(const float* __restrict__ h, int M) {
    int c = threadIdx.x;                 // 128 threads
    int m0 = blockIdx.x * 512;
    int mend = min(m0 + 512, M);
    float s = 0.f;
    for (int m = m0; m < mend; m++) s += h[(size_t)m * DHID + c];
    atomicAdd(&g_hsum[c], s);
}

// ---------------------------------------------------------------------------
// hcov: g_H += (h - mh)^T (h - mh)   via TF32 MMA, 512 rows per block.
// smem: hs[128 i][132 m] (transposed, centered, tf32) + mh[128].
// ---------------------------------------------------------------------------
__global__ __launch_bounds__(256, 1)
void hcov_kernel(const float* __restrict__ h, int M, float Minv) {
    extern __shared__ float sm[];
    float (*hs)[SSTR] = (float(*)[SSTR])sm;
    float* mh = sm + 128 * SSTR;

    const int tid = threadIdx.x, lane = tid & 31, wid = tid >> 5;
    const int wm = (wid & 1) * 64, wn = (wid >> 1) * 32;
    const int arow = wm + (lane >> 2), brow = wn + (lane >> 2), kl = lane & 3;

    if (tid < 128) mh[tid] = g_hsum[tid] * Minv;

    float acc[4][4][4];
#pragma unroll
    for (int i = 0; i < 4; i++)
#pragma unroll
        for (int j = 0; j < 4; j++)
#pragma unroll
            for (int c = 0; c < 4; c++) acc[i][j][c] = 0.f;

    const int m0 = blockIdx.x * 512;
    for (int sub = 0; sub < 4; sub++) {
        __syncthreads();
        for (int idx = tid; idx < 128 * 32; idx += 256) {
            int ml = idx >> 5, c4 = (idx & 31) * 4;
            int m = m0 + sub * 128 + ml;
            float4 v = make_float4(0.f, 0.f, 0.f, 0.f);
            if (m < M) {
                v = __ldg((const float4*)(h + (size_t)m * DHID + c4));
                v.x -= mh[c4]; v.y -= mh[c4 + 1]; v.z -= mh[c4 + 2]; v.w -= mh[c4 + 3];
                v = cvt_tf32x4(v);
            }
            hs[c4 + 0][ml] = v.x; hs[c4 + 1][ml] = v.y;
            hs[c4 + 2][ml] = v.z; hs[c4 + 3][ml] = v.w;
        }
        __syncthreads();
        mma_block_k128(hs, hs, acc, arow, brow, kl);
    }

#pragma unroll
    for (int nt = 0; nt < 4; nt++) {
        int col = wn + nt * 8 + (lane & 3) * 2;
#pragma unroll
        for (int mt = 0; mt < 4; mt++) {
#pragma unroll
            for (int hh = 0; hh < 2; hh++) {
                int row = wm + mt * 16 + (lane >> 2) + 8 * hh;
                atomicAdd(&g_H[row * 128 + col],     acc[mt][nt][2 * hh]);
                atomicAdd(&g_H[row * 128 + col + 1], acc[mt][nt][2 * hh + 1]);
            }
        }
    }
}

// ---------------------------------------------------------------------------
// bnprep: per channel c: var = w^T H w / M, mu' = w . mh;
//   scale = gamma * rsqrt(var+eps), shift = beta - mu'*scale   (bd1 cancels
//   against the missing bias in the fused decoder's GEMM1 accumulator)
// ---------------------------------------------------------------------------
__global__ void bnprep_kernel(const float* __restrict__ Wd1,
                              const float* __restrict__ gamma,
                              const float* __restrict__ beta, float Minv) {
    const int c = blockIdx.x;            // 512 blocks
    const int k = threadIdx.x;           // 128 threads
    const int lane = k & 31, wid = k >> 5;
    __shared__ float w[128];
    __shared__ float rq[4], rmu[4];

    w[k] = Wd1[(size_t)c * 128 + k];
    __syncthreads();

    float t = 0.f;
#pragma unroll 8
    for (int i = 0; i < 128; i++) t = fmaf(w[i], g_H[i * 128 + k], t);
    float q  = t * w[k];
    float mu = w[k] * g_hsum[k] * Minv;

#pragma unroll
    for (int off = 16; off; off >>= 1) {
        q  += __shfl_down_sync(0xffffffffu, q, off);
        mu += __shfl_down_sync(0xffffffffu, mu, off);
    }
    if (lane == 0) { rq[wid] = q; rmu[wid] = mu; }
    __syncthreads();
    if (k == 0) {
        float Q  = rq[0] + rq[1] + rq[2] + rq[3];
        float MU = rmu[0] + rmu[1] + rmu[2] + rmu[3];
        float var = fmaxf(Q * Minv, 0.f);
        float sc = gamma[c] * rsqrtf(var + 1e-5f);
        g_scale[c] = sc;
        g_shift[c] = beta[c] - MU * sc;
    }
}

// ---------------------------------------------------------------------------
// fused decoder: rec = leaky(bn(h@Wd1^T+bd1),0.01) @ Wd2^T + bd2
// per 128-row block: h in smem; 4 chunks of 128 cols:
//   GEMM1 -> bn+leaky (regs) -> ds smem -> GEMM2 accumulates rec.
// ---------------------------------------------------------------------------
__global__ __launch_bounds__(256, 1)
void dec_fused_kernel(const float* __restrict__ h,
                      const float* __restrict__ Wd1,
                      const float* __restrict__ Wd2,
                      const float* __restrict__ bd2,
                      float* __restrict__ rec, int M) {
    extern __shared__ float sm[];
    float (*hs)[SSTR] = (float(*)[SSTR])sm;                    // h tile [m][k]
    float (*ws)[SSTR] = (float(*)[SSTR])(sm + 128 * SSTR);     // weight chunk [n][k]
    float (*ds)[SSTR] = (float(*)[SSTR])(sm + 2 * 128 * SSTR); // bn(d) chunk [m][k]

    const int tid = threadIdx.x, lane = tid & 31, wid = tid >> 5;
    const int wm = (wid & 1) * 64, wn = (wid >> 1) * 32;
    const int arow = wm + (lane >> 2), brow = wn + (lane >> 2), kl = lane & 3;
    const int m0 = blockIdx.x * 128;

    // stage h tile (tf32)
    for (int idx = tid; idx < 128 * 32; idx += 256) {
        int ml = idx >> 5, c4 = (idx & 31) * 4;
        int m = m0 + ml;
        float4 v = make_float4(0.f, 0.f, 0.f, 0.f);
        if (m < M) v = cvt_tf32x4(__ldg((const float4*)(h + (size_t)m * DHID + c4)));
        *(float4*)&hs[ml][c4] = v;
    }

    float racc[4][4][4];
#pragma unroll
    for (int i = 0; i < 4; i++)
#pragma unroll
        for (int j = 0; j < 4; j++)
#pragma unroll
            for (int c = 0; c < 4; c++) racc[i][j][c] = 0.f;

    for (int ch = 0; ch < 4; ch++) {
        __syncthreads();   // prev GEMM2 done reading ds/ws; h staging done (ch=0)
        // stage Wd1 chunk: rows ch*128..+128 of Wd1[512][128]
        for (int idx = tid; idx < 128 * 32; idx += 256) {
            int n = idx >> 5, c4 = (idx & 31) * 4;
            float4 v = cvt_tf32x4(__ldg((const float4*)(Wd1 + (size_t)(ch * 128 + n) * 128 + c4)));
            *(float4*)&ws[n][c4] = v;
        }
        __syncthreads();

        float dacc[4][4][4];
#pragma unroll
        for (int i = 0; i < 4; i++)
#pragma unroll
            for (int j = 0; j < 4; j++)
#pragma unroll
                for (int c = 0; c < 4; c++) dacc[i][j][c] = 0.f;
        mma_block_k128(hs, ws, dacc, arow, brow, kl);

        __syncthreads();   // all warps finished reading ws (and ds free)

        // bn + leaky -> ds ; restage ws = Wd2 chunk
#pragma unroll
        for (int nt = 0; nt < 4; nt++) {
            int coll = wn + nt * 8 + (lane & 3) * 2;
            int cg = ch * 128 + coll;
            float sc0 = g_scale[cg], sc1 = g_scale[cg + 1];
            float sh0 = g_shift[cg], sh1 = g_shift[cg + 1];
#pragma unroll
            for (int mt = 0; mt < 4; mt++) {
#pragma unroll
                for (int hh = 0; hh < 2; hh++) {
                    int row = wm + mt * 16 + (lane >> 2) + 8 * hh;
                    float v0 = fmaf(dacc[mt][nt][2 * hh],     sc0, sh0);
                    float v1 = fmaf(dacc[mt][nt][2 * hh + 1], sc1, sh1);
                    v0 = v0 >= 0.f ? v0 : 0.01f * v0;
                    v1 = v1 >= 0.f ? v1 : 0.01f * v1;
                    ds[row][coll]     = __uint_as_float(f2tf32(v0));
                    ds[row][coll + 1] = __uint_as_float(f2tf32(v1));
                }
            }
        }
        for (int idx = tid; idx < 128 * 32; idx += 256) {
            int n = idx >> 5, c4 = (idx & 31) * 4;
            float4 v = cvt_tf32x4(__ldg((const float4*)(Wd2 + (size_t)n * DDEC + ch * 128 + c4)));
            *(float4*)&ws[n][c4] = v;
        }
        __syncthreads();

        mma_block_k128(ds, ws, racc, arow, brow, kl);
    }

    // epilogue: + bd2
#pragma unroll
    for (int nt = 0; nt < 4; nt++) {
        int col = wn + nt * 8 + (lane & 3) * 2;
        float b0 = __ldg(&bd2[col]), b1 = __ldg(&bd2[col + 1]);
#pragma unroll
        for (int mt = 0; mt < 4; mt++) {
#pragma unroll
            for (int hh = 0; hh < 2; hh++) {
                int r = m0 + wm + mt * 16 + (lane >> 2) + 8 * hh;
                if (r >= M) continue;
                *(float2*)&rec[(size_t)r * DIN + col] =
                    make_float2(racc[mt][nt][2 * hh] + b0, racc[mt][nt][2 * hh + 1] + b1);
            }
        }
    }
}

// ---------------------------------------------------------------------------
// host launcher
// ---------------------------------------------------------------------------
extern "C" void kernel_launch(void* const* d_in, const int* in_sizes, int n_in,
                              void* d_out, int out_size) {
    const float* x     = (const float*)d_in[0];
    const int*   ei    = (const int*)d_in[1];
    const float* Wl    = (const float*)d_in[2];
    const float* bl    = (const float*)d_in[3];
    const float* Wr    = (const float*)d_in[4];
    const float* Wp    = (const float*)d_in[5];
    const float* bp    = (const float*)d_in[6];
    const float* ap    = (const float*)d_in[7];
    const float* Wd1   = (const float*)d_in[8];
    const float* gamma = (const float*)d_in[10];
    const float* beta  = (const float*)d_in[11];
    const float* Wd2   = (const float*)d_in[12];
    const float* bd2   = (const float*)d_in[13];

    const int M = in_sizes[0] / DIN;
    const int E = in_sizes[1] / 2;
    const float Minv = 1.0f / (float)M;

    float* out = (float*)d_out;
    float* h_out   = out;
    float* z_out   = out + (size_t)M * DHID;
    float* rec_out = out + (size_t)2 * M * DHID;
    float* tgt_out = out + (size_t)3 * M * DHID;

    const int HCOV_SMEM = (128 * SSTR + 128) * 4;
    const int DEC_SMEM  = 3 * 128 * SSTR * 4;
    static bool attr_set = false;
    if (!attr_set) {
        cudaFuncSetAttribute(hcov_kernel, cudaFuncAttributeMaxDynamicSharedMemorySize, HCOV_SMEM);
        cudaFuncSetAttribute(dec_fused_kernel, cudaFuncAttributeMaxDynamicSharedMemorySize, DEC_SMEM);
        attr_set = true;
    }

    // 1. zero scratch + copy target
    init_kernel<<<2048, 256>>>((const float4*)x, (float4*)tgt_out, M);

    // 2. edge scatter
    scatter_kernel<<<(E + 255) / 256, 256>>>(ei, (const float4*)x, E);

    const int gm = (M + BM - 1) / BM;

    // 3. encoder (degree division fused into A loader)
    gemm_tc<0, 256, 128><<<dim3(gm, 1), 256>>>(nullptr, x, Wl, Wr, bl, ap, h_out, M);

    // 4. projection
    gemm_tc<1, 128, 128><<<dim3(gm, 1), 256>>>(h_out, nullptr, Wp, nullptr, bp, ap, z_out, M);

    // 5. analytic BN stats: colsum -> centered covariance -> scale/shift
    colsum_kernel<<<(M + 511) / 512, 128>>>(h_out, M);
    hcov_kernel<<<(M + 511) / 512, 256, HCOV_SMEM>>>(h_out, M, Minv);
    bnprep_kernel<<<DDEC, 128>>>(Wd1, gamma, beta, Minv);

    // 6. fused decoder
    dec_fused_kernel<<<gm, 256, DEC_SMEM>>>(h_out, Wd1, Wd2, bd2, rec_out, M);
}